// round 9
// baseline (speedup 1.0000x reference)
#include <cuda_runtime.h>
#include <math.h>

// Shapes (fixed by setup_inputs): B=4, C=64, C2=32, N=1024, V=20
#define NP 4096            // B*N pairs
#define CNT1 81920.0f      // B*N*V
#define CNT2 1638400.0f    // B*N*V*V

typedef unsigned long long ull;

// Scratch (allocation-free rule: __device__ globals; zero-initialized at load)
__device__ float g_xpre[NP * 32 * 20];        // masked pre-BN embed output, (pair, o, v)
__device__ float g_ut[(size_t)NP * 128 * 20]; // rows 0..63 = u, 64..127 = t, (pair, row, v)
__device__ float g_acc[384 * 256];            // stat counters, stride 256 floats (1024B -> distinct L2 slices)

// counter slots: [0,32)=sum1 [32,64)=sq1 [64,128)=SU [128,192)=SUQ [192,256)=ST [256,320)=STQ [320,384)=CROSS
// Replay protocol (graph-safe, no dedicated zeroing kernel):
//   K1 block0 zeroes [64,384)  (K3 writes them later in the same replay)
//   K1 accumulates [0,64);  K3 reads [0,64), accumulates [64,384);  K5 reads [64,384)
//   K5 block0 zeroes [0,64)    (their readers, K3, already finished)
#define ACC(i) g_acc[(i) * 256]

// ---- packed fp32x2 helpers (Blackwell FFMA2 path) ----
__device__ __forceinline__ void fma2(ull& d, ull a, ull b) {
    asm("fma.rn.f32x2 %0, %1, %2, %0;" : "+l"(d) : "l"(a), "l"(b));
}
__device__ __forceinline__ ull pack2(float x) {
    ull r; unsigned int u = __float_as_uint(x);
    asm("mov.b64 %0, {%1, %1};" : "=l"(r) : "r"(u));
    return r;
}
__device__ __forceinline__ float2 unpack2(ull v) {
    unsigned int lo, hi;
    asm("mov.b64 {%0, %1}, %2;" : "=r"(lo), "=r"(hi) : "l"(v));
    return make_float2(__uint_as_float(lo), __uint_as_float(hi));
}

// ---------------- K1: embed GEMM (f32x2) + mask + BN1 partial stats ----------------
// grid 2048, block 320: two 160-thread pair-groups (pg), 2 pairs/block.
// Within a group: o = r&31, vg = r>>5.
__global__ void __launch_bounds__(320, 4)
k1_embed(const float* __restrict__ feats, const float* __restrict__ mask,
         const float* __restrict__ w_embed, const float* __restrict__ b_embed) {
    __shared__ ull sW2[64 * 32];                     // packed (w,w) per [c][o], 16KB
    __shared__ __align__(16) float sf[2][64 * 20];   // feats tiles, one per pair-group
    __shared__ __align__(16) float sm[2][20];
    __shared__ float red_s[320], red_q[320];

    int t = threadIdx.x;
    int pg = t / 160, r = t - pg * 160;
    int o = r & 31, vg = r >> 5;

    if (blockIdx.x == 0) ACC(64 + t) = 0.0f;         // zero BN2 slots for this replay (320 slots)

    for (int i = t; i < 2048; i += 320) {
        int oo = i >> 6, c = i & 63;
        sW2[c * 32 + oo] = pack2(w_embed[i]);
    }
    float bo = b_embed[o];

    int pair = blockIdx.x * 2 + pg;
    int b = pair >> 10, n = pair & 1023;
    if (r < 20) sm[pg][r] = mask[pair * 20 + r];
    const float* fbase = feats + (size_t)b * 64 * 20480 + n * 20;
    for (int i = r; i < 320; i += 160) {             // 64 rows x 5 float4
        int c = i / 5, q = i - 5 * c;
        *(float4*)&sf[pg][c * 20 + 4 * q] = *(const float4*)&fbase[c * 20480 + 4 * q];
    }
    __syncthreads();

    ull acc0 = pack2(bo), acc1 = acc0;               // v = 4vg..4vg+3
#pragma unroll
    for (int c = 0; c < 64; c++) {
        ull w2 = sW2[c * 32 + o];                    // LDS.64, lane-consecutive, conflict-free
        ulonglong2 x = *(const ulonglong2*)&sf[pg][c * 20 + 4 * vg];  // broadcast
        fma2(acc0, x.x, w2);
        fma2(acc1, x.y, w2);
    }
    float2 f0 = unpack2(acc0), f1 = unpack2(acc1);
    float4 m4 = *(const float4*)&sm[pg][4 * vg];
    float4 rr;
    rr.x = f0.x * m4.x; rr.y = f0.y * m4.y; rr.z = f1.x * m4.z; rr.w = f1.y * m4.w;
    *(float4*)&g_xpre[(size_t)pair * 640 + o * 20 + 4 * vg] = rr;

    red_s[t] = rr.x + rr.y + rr.z + rr.w;
    red_q[t] = rr.x * rr.x + rr.y * rr.y + rr.z * rr.z + rr.w * rr.w;
    __syncthreads();
    if (t < 32) {                                    // all 10 groups of 32 have o == t
        float s = 0.f, q = 0.f;
#pragma unroll
        for (int k = 0; k < 10; k++) { s += red_s[t + 32 * k]; q += red_q[t + 32 * k]; }
        atomicAdd(&ACC(t), s);
        atomicAdd(&ACC(32 + t), q);
    }
}

// ---------------- K3: BN1-finalize (per block) + [u;t] GEMM -> g_ut + BN2 partial stats ----------------
// grid 2048, block 128 (thread = output row: 0..63 -> u row, 64..127 -> t row), 2 pairs/block
__global__ void __launch_bounds__(128, 8)
k3_conv(const float* __restrict__ mask, const float* __restrict__ w_conv,
        const float* __restrict__ g_embed, const float* __restrict__ be_embed) {
    __shared__ __align__(16) float sx[640];  // activated x, [c][v]
    __shared__ __align__(16) float sm[20];
    __shared__ float sst[64];
    __shared__ float s_sc[32], s_sh[32];

    int t = threadIdx.x;
    if (t < 32) {                            // redundant per-block BN1 finalize (reads L2-cached counters)
        float inv = 1.0f / CNT1;
        float m = ACC(t) * inv;
        float var = ACC(32 + t) * inv - m * m;
        float sc = g_embed[t] * rsqrtf(var + 1e-5f);
        s_sc[t] = sc;
        s_sh[t] = be_embed[t] - m * sc;
    }

    float W[32];
    if (t < 64) {
#pragma unroll
        for (int c = 0; c < 32; c++) W[c] = w_conv[t * 64 + c] - w_conv[t * 64 + 32 + c];
    } else {
#pragma unroll
        for (int c = 0; c < 32; c++) W[c] = w_conv[(t - 64) * 64 + 32 + c];
    }

    float a_sum = 0.f, a_sq = 0.f, a_cr = 0.f;

    for (int p2 = 0; p2 < 2; p2++) {
        int pair = blockIdx.x * 2 + p2;
        __syncthreads();  // covers s_sc init (iter 0) and tile reuse (iter 1)
        if (t < 20) sm[t] = mask[pair * 20 + t];
        __syncthreads();
        // activate: 160 float4s, 128 threads
        for (int i = t; i < 160; i += 128) {
            int c = i / 5, q = i - 5 * c;
            float4 x = *(const float4*)&g_xpre[(size_t)pair * 640 + c * 20 + 4 * q];
            float sc = s_sc[c], sh = s_sh[c];
            int vb = 4 * q;
            float4 r;
            r.x = sm[vb + 0] * fmaxf(fmaf(x.x, sc, sh), 0.0f);
            r.y = sm[vb + 1] * fmaxf(fmaf(x.y, sc, sh), 0.0f);
            r.z = sm[vb + 2] * fmaxf(fmaf(x.z, sc, sh), 0.0f);
            r.w = sm[vb + 3] * fmaxf(fmaf(x.w, sc, sh), 0.0f);
            *(float4*)&sx[c * 20 + 4 * q] = r;
        }
        __syncthreads();

        ull acc[10];
#pragma unroll
        for (int j = 0; j < 10; j++) acc[j] = 0ull;
#pragma unroll
        for (int c = 0; c < 32; c++) {
            ull w2 = pack2(W[c]);
            const ulonglong2* row = (const ulonglong2*)&sx[c * 20];
#pragma unroll
            for (int q = 0; q < 5; q++) {
                ulonglong2 x = row[q];
                fma2(acc[2 * q], x.x, w2);
                fma2(acc[2 * q + 1], x.y, w2);
            }
        }
        // store row to g_ut (5 x STG.128)
        ulonglong2* gout = (ulonglong2*)&g_ut[((size_t)pair * 128 + t) * 20];
#pragma unroll
        for (int q = 0; q < 5; q++) {
            ulonglong2 s2; s2.x = acc[2 * q]; s2.y = acc[2 * q + 1];
            gout[q] = s2;
        }
        float psum = 0.f, psq = 0.f;
#pragma unroll
        for (int j = 0; j < 10; j++) {
            float2 f = unpack2(acc[j]);
            psum += f.x + f.y;
            psq += fmaf(f.x, f.x, f.y * f.y);
        }
        a_sum += psum; a_sq += psq;
        if (t >= 64) sst[t - 64] = psum;
        __syncthreads();
        if (t < 64) a_cr += psum * sst[t];  // per-pair (sum_v u[o])·(sum_v t[o]) cross term
    }

    if (t < 64) {
        atomicAdd(&ACC(64 + t), a_sum);
        atomicAdd(&ACC(128 + t), a_sq);
        atomicAdd(&ACC(320 + t), a_cr);
    } else {
        int o = t - 64;
        atomicAdd(&ACC(192 + o), a_sum);
        atomicAdd(&ACC(256 + o), a_sq);
    }
}

// ---------------- K5: BN2-finalize (per block) + streaming max-aggregate epilogue ----------------
// grid 1024, block 256; 4 pairs/block (same b per block).
__global__ void __launch_bounds__(256, 6)
k5_out(const float* __restrict__ feats, const float* __restrict__ mask,
       const float* __restrict__ g_conv, const float* __restrict__ be_conv,
       float* __restrict__ out) {
    __shared__ float sTmax[4 * 64], sTmin[4 * 64];
    __shared__ float sm20[4 * 20];
    __shared__ float sA[64], sC[64];

    int t = threadIdx.x;
    int pair0 = blockIdx.x * 4;
    int b = pair0 >> 10, n0 = pair0 & 1023;

    if (t < 64) {                            // redundant per-block BN2 finalize
        float SU = ACC(64 + t), SUQ = ACC(128 + t);
        float ST = ACC(192 + t), STQ = ACC(256 + t);
        float CR = ACC(320 + t);
        float m = 20.0f * (SU + ST) / CNT2;
        float ey2 = (20.0f * (SUQ + STQ) + 2.0f * CR) / CNT2;
        float var = ey2 - m * m;
        float a = g_conv[t] * rsqrtf(var + 1e-5f);
        sA[t] = a;
        sC[t] = be_conv[t] - m * a;
    }
    if (blockIdx.x == 0 && t >= 192) ACC(t - 192) = 0.0f;   // zero BN1 slots [0,64) for next replay
    if (t >= 64 && t < 144) sm20[t - 64] = mask[pair0 * 20 + (t - 64)];

    // Phase T: thread = (p, o); reduce t-row over v
    {
        int p = t >> 6, o = t & 63;
        const float4* trow = (const float4*)&g_ut[((size_t)(pair0 + p) * 128 + 64 + o) * 20];
        float tmax = -3.4e38f, tmin = 3.4e38f;
#pragma unroll
        for (int q = 0; q < 5; q++) {
            float4 x = trow[q];
            tmax = fmaxf(tmax, fmaxf(fmaxf(x.x, x.y), fmaxf(x.z, x.w)));
            tmin = fminf(tmin, fminf(fminf(x.x, x.y), fminf(x.z, x.w)));
        }
        sTmax[p * 64 + o] = tmax;
        sTmin[p * 64 + o] = tmin;
    }
    __syncthreads();

    // Phase OUT: 1280 float4s (64 o x 4 p x 5 q), 5 iters x 256 threads
    const float4* f4p = (const float4*)feats;
    float4* o4p = (float4*)out;
#pragma unroll
    for (int k = 0; k < 5; k++) {
        int i = t + k * 256;                // 0..1279
        int oi = i / 20, j = i - 20 * oi;   // oi 0..63
        int p = j / 5, q = j - 5 * p;
        float a = sA[oi], cc = sC[oi];
        // max_w relu(a*(u + t_w) + c) = relu(a*(u + (a>=0 ? max t : min t)) + c)
        float Ts = (a >= 0.0f) ? sTmax[p * 64 + oi] : sTmin[p * 64 + oi];
        float4 u4 = *(const float4*)&g_ut[((size_t)(pair0 + p) * 128 + oi) * 20 + 4 * q];
        size_t base4 = ((size_t)((b * 64 + oi) * 1024 + n0 + p)) * 5 + q;
        float4 f4 = f4p[base4];
        int vb = 4 * q;
        float4 r;
        r.x = f4.x + sm20[p * 20 + vb + 0] * fmaxf(fmaf(a, u4.x + Ts, cc), 0.0f);
        r.y = f4.y + sm20[p * 20 + vb + 1] * fmaxf(fmaf(a, u4.y + Ts, cc), 0.0f);
        r.z = f4.z + sm20[p * 20 + vb + 2] * fmaxf(fmaf(a, u4.z + Ts, cc), 0.0f);
        r.w = f4.w + sm20[p * 20 + vb + 3] * fmaxf(fmaf(a, u4.w + Ts, cc), 0.0f);
        o4p[base4] = r;
    }
}

extern "C" void kernel_launch(void* const* d_in, const int* in_sizes, int n_in,
                              void* d_out, int out_size) {
    const float* feats   = (const float*)d_in[0];  // (4,64,1024,20)
    const float* mask    = (const float*)d_in[1];  // (4,1024,20)
    const float* w_embed = (const float*)d_in[2];  // (32,64)
    const float* b_embed = (const float*)d_in[3];  // (32)
    const float* g_embed = (const float*)d_in[4];  // (32)
    const float* be_embed= (const float*)d_in[5];  // (32)
    const float* w_conv  = (const float*)d_in[6];  // (64,64)
    const float* g_conv  = (const float*)d_in[7];  // (64)
    const float* be_conv = (const float*)d_in[8];  // (64)
    float* out = (float*)d_out;

    k1_embed<<<2048, 320>>>(feats, mask, w_embed, b_embed);
    k3_conv<<<2048, 128>>>(mask, w_conv, g_embed, be_embed);
    k5_out<<<1024, 256>>>(feats, mask, g_conv, be_conv, out);
}

// round 11
// speedup vs baseline: 1.2930x; 1.2930x over previous
#include <cuda_runtime.h>
#include <math.h>

// Shapes (fixed by setup_inputs): B=4, C=64, C2=32, N=1024, V=20
#define NP 4096            // B*N pairs
#define CNT1 81920.0f      // B*N*V
#define CNT2 1638400.0f    // B*N*V*V

typedef unsigned long long ull;

// Scratch (allocation-free rule: __device__ globals; zero-initialized at load)
__device__ float g_xpre[NP * 32 * 20];        // masked pre-BN embed output, (pair, o, v)
__device__ float g_ut[(size_t)NP * 128 * 20]; // rows 0..63 = u, 64..127 = t, (pair, row, v)
__device__ float g_acc[384 * 256];            // stat counters, stride 256 floats (1024B -> distinct L2 slices)

// counter slots: [0,32)=sum1 [32,64)=sq1 [64,128)=SU [128,192)=SUQ [192,256)=ST [256,320)=STQ [320,384)=CROSS
// Replay protocol (graph-safe): K1-b0 zeroes [64,384) (320 threads); K5-b0 zeroes [0,64).
#define ACC(i) g_acc[(i) * 256]

// ---- packed fp32x2 helpers (proven in passing runs R4/R9) ----
__device__ __forceinline__ void fma2(ull& d, ull a, ull b) {
    asm("fma.rn.f32x2 %0, %1, %2, %0;" : "+l"(d) : "l"(a), "l"(b));
}
__device__ __forceinline__ ull pack2(float x) {
    ull r; unsigned int u = __float_as_uint(x);
    asm("mov.b64 %0, {%1, %1};" : "=l"(r) : "r"(u));
    return r;
}
__device__ __forceinline__ float2 unpack2(ull v) {
    unsigned int lo, hi;
    asm("mov.b64 {%0, %1}, %2;" : "=r"(lo), "=r"(hi) : "l"(v));
    return make_float2(__uint_as_float(lo), __uint_as_float(hi));
}

// ---------------- K1: embed GEMM (f32x2) + mask + BN1 partial stats ----------------
// grid 1024, block 320: two 160-thread pair-groups (pg), 2 iterations -> 4 pairs/block.
// Within a group: o = r&31, vg = r>>5.  [text proven at the 99.0us run + R9 zeroing line]
__global__ void __launch_bounds__(320, 4)
k1_embed(const float* __restrict__ feats, const float* __restrict__ mask,
         const float* __restrict__ w_embed, const float* __restrict__ b_embed) {
    __shared__ ull sW2[64 * 32];                     // packed (w,w) per [c][o], 16KB
    __shared__ __align__(16) float sf[2][64 * 20];   // feats tiles, one per pair-group
    __shared__ __align__(16) float sm[2][20];
    __shared__ float red_s[320], red_q[320];

    int t = threadIdx.x;
    int pg = t / 160, r = t - pg * 160;
    int o = r & 31, vg = r >> 5;

    if (blockIdx.x == 0) ACC(64 + t) = 0.0f;         // zero BN2 slots [64,384) for this replay

    for (int i = t; i < 2048; i += 320) {
        int oo = i >> 6, c = i & 63;
        sW2[c * 32 + oo] = pack2(w_embed[i]);
    }
    float bo = b_embed[o];
    float ssum = 0.f, ssq = 0.f;

    for (int it = 0; it < 2; it++) {
        int pair = blockIdx.x * 4 + it * 2 + pg;
        int b = pair >> 10, n = pair & 1023;
        __syncthreads();                 // covers sW2 init on it==0, tile reuse after
        if (r < 20) sm[pg][r] = mask[pair * 20 + r];
        const float* fbase = feats + (size_t)b * 64 * 20480 + n * 20;
        for (int i = r; i < 320; i += 160) {         // 64 rows x 5 float4
            int c = i / 5, q = i - 5 * c;
            *(float4*)&sf[pg][c * 20 + 4 * q] = *(const float4*)&fbase[c * 20480 + 4 * q];
        }
        __syncthreads();

        ull acc0 = pack2(bo), acc1 = acc0;           // v = 4vg..4vg+3
#pragma unroll
        for (int c = 0; c < 64; c++) {
            ull w2 = sW2[c * 32 + o];                // LDS.64, lane-consecutive, conflict-free
            ulonglong2 x = *(const ulonglong2*)&sf[pg][c * 20 + 4 * vg];  // broadcast
            fma2(acc0, x.x, w2);
            fma2(acc1, x.y, w2);
        }
        float2 f0 = unpack2(acc0), f1 = unpack2(acc1);
        float4 m4 = *(const float4*)&sm[pg][4 * vg];
        float4 rr;
        rr.x = f0.x * m4.x; rr.y = f0.y * m4.y; rr.z = f1.x * m4.z; rr.w = f1.y * m4.w;
        *(float4*)&g_xpre[(size_t)pair * 640 + o * 20 + 4 * vg] = rr;
        ssum += rr.x + rr.y + rr.z + rr.w;
        ssq += rr.x * rr.x + rr.y * rr.y + rr.z * rr.z + rr.w * rr.w;
    }
    red_s[t] = ssum; red_q[t] = ssq;
    __syncthreads();
    if (t < 32) {                                    // all 10 groups of 32 have o == t
        float s = 0.f, q = 0.f;
#pragma unroll
        for (int k = 0; k < 10; k++) { s += red_s[t + 32 * k]; q += red_q[t + 32 * k]; }
        atomicAdd(&ACC(t), s);
        atomicAdd(&ACC(32 + t), q);
    }
}

// ---------------- K3: BN1-finalize (per block) + [u;t] GEMM -> g_ut + BN2 partial stats ----------------
// grid 1024, block 128 (thread = output row: 0..63 -> u row, 64..127 -> t row), 4 pairs/block
// [R9-proven text; loop widened to 4 pairs as proven in the 99.0us run's K3]
__global__ void __launch_bounds__(128, 8)
k3_conv(const float* __restrict__ mask, const float* __restrict__ w_conv,
        const float* __restrict__ g_embed, const float* __restrict__ be_embed) {
    __shared__ __align__(16) float sx[640];  // activated x, [c][v]
    __shared__ __align__(16) float sm[20];
    __shared__ float sst[64];
    __shared__ float s_sc[32], s_sh[32];

    int t = threadIdx.x;
    if (t < 32) {                            // redundant per-block BN1 finalize (L2-cached counters)
        float inv = 1.0f / CNT1;
        float m = ACC(t) * inv;
        float var = ACC(32 + t) * inv - m * m;
        float sc = g_embed[t] * rsqrtf(var + 1e-5f);
        s_sc[t] = sc;
        s_sh[t] = be_embed[t] - m * sc;
    }

    float W[32];
    if (t < 64) {
#pragma unroll
        for (int c = 0; c < 32; c++) W[c] = w_conv[t * 64 + c] - w_conv[t * 64 + 32 + c];
    } else {
#pragma unroll
        for (int c = 0; c < 32; c++) W[c] = w_conv[(t - 64) * 64 + 32 + c];
    }

    float a_sum = 0.f, a_sq = 0.f, a_cr = 0.f;

    for (int p4 = 0; p4 < 4; p4++) {
        int pair = blockIdx.x * 4 + p4;
        __syncthreads();  // covers s_sc init (iter 0) and tile reuse
        if (t < 20) sm[t] = mask[pair * 20 + t];
        __syncthreads();
        // activate: 160 float4s, 128 threads
        for (int i = t; i < 160; i += 128) {
            int c = i / 5, q = i - 5 * c;
            float4 x = *(const float4*)&g_xpre[(size_t)pair * 640 + c * 20 + 4 * q];
            float sc = s_sc[c], sh = s_sh[c];
            int vb = 4 * q;
            float4 r;
            r.x = sm[vb + 0] * fmaxf(fmaf(x.x, sc, sh), 0.0f);
            r.y = sm[vb + 1] * fmaxf(fmaf(x.y, sc, sh), 0.0f);
            r.z = sm[vb + 2] * fmaxf(fmaf(x.z, sc, sh), 0.0f);
            r.w = sm[vb + 3] * fmaxf(fmaf(x.w, sc, sh), 0.0f);
            *(float4*)&sx[c * 20 + 4 * q] = r;
        }
        __syncthreads();

        ull acc[10];
#pragma unroll
        for (int j = 0; j < 10; j++) acc[j] = 0ull;
#pragma unroll
        for (int c = 0; c < 32; c++) {
            ull w2 = pack2(W[c]);
            const ulonglong2* row = (const ulonglong2*)&sx[c * 20];
#pragma unroll
            for (int q = 0; q < 5; q++) {
                ulonglong2 x = row[q];
                fma2(acc[2 * q], x.x, w2);
                fma2(acc[2 * q + 1], x.y, w2);
            }
        }
        // store row to g_ut (5 x STG.128)
        ulonglong2* gout = (ulonglong2*)&g_ut[((size_t)pair * 128 + t) * 20];
#pragma unroll
        for (int q = 0; q < 5; q++) {
            ulonglong2 s2; s2.x = acc[2 * q]; s2.y = acc[2 * q + 1];
            gout[q] = s2;
        }
        float psum = 0.f, psq = 0.f;
#pragma unroll
        for (int j = 0; j < 10; j++) {
            float2 f = unpack2(acc[j]);
            psum += f.x + f.y;
            psq += fmaf(f.x, f.x, f.y * f.y);
        }
        a_sum += psum; a_sq += psq;
        if (t >= 64) sst[t - 64] = psum;
        __syncthreads();
        if (t < 64) a_cr += psum * sst[t];  // per-pair (sum_v u[o])·(sum_v t[o]) cross term
    }

    if (t < 64) {
        atomicAdd(&ACC(64 + t), a_sum);
        atomicAdd(&ACC(128 + t), a_sq);
        atomicAdd(&ACC(320 + t), a_cr);
    } else {
        int o = t - 64;
        atomicAdd(&ACC(192 + o), a_sum);
        atomicAdd(&ACC(256 + o), a_sq);
    }
}

// ---------------- K5: BN2-finalize (per block) + streaming max-aggregate epilogue ----------------
// grid 1024, block 256; 4 pairs/block (same b per block).  [R9-proven text verbatim]
__global__ void __launch_bounds__(256, 6)
k5_out(const float* __restrict__ feats, const float* __restrict__ mask,
       const float* __restrict__ g_conv, const float* __restrict__ be_conv,
       float* __restrict__ out) {
    __shared__ float sTmax[4 * 64], sTmin[4 * 64];
    __shared__ float sm20[4 * 20];
    __shared__ float sA[64], sC[64];

    int t = threadIdx.x;
    int pair0 = blockIdx.x * 4;
    int b = pair0 >> 10, n0 = pair0 & 1023;

    if (t < 64) {                            // redundant per-block BN2 finalize
        float SU = ACC(64 + t), SUQ = ACC(128 + t);
        float ST = ACC(192 + t), STQ = ACC(256 + t);
        float CR = ACC(320 + t);
        float m = 20.0f * (SU + ST) / CNT2;
        float ey2 = (20.0f * (SUQ + STQ) + 2.0f * CR) / CNT2;
        float var = ey2 - m * m;
        float a = g_conv[t] * rsqrtf(var + 1e-5f);
        sA[t] = a;
        sC[t] = be_conv[t] - m * a;
    }
    if (blockIdx.x == 0 && t >= 192) ACC(t - 192) = 0.0f;   // zero BN1 slots [0,64) for next replay
    if (t >= 64 && t < 144) sm20[t - 64] = mask[pair0 * 20 + (t - 64)];

    // Phase T: thread = (p, o); reduce t-row over v
    {
        int p = t >> 6, o = t & 63;
        const float4* trow = (const float4*)&g_ut[((size_t)(pair0 + p) * 128 + 64 + o) * 20];
        float tmax = -3.4e38f, tmin = 3.4e38f;
#pragma unroll
        for (int q = 0; q < 5; q++) {
            float4 x = trow[q];
            tmax = fmaxf(tmax, fmaxf(fmaxf(x.x, x.y), fmaxf(x.z, x.w)));
            tmin = fminf(tmin, fminf(fminf(x.x, x.y), fminf(x.z, x.w)));
        }
        sTmax[p * 64 + o] = tmax;
        sTmin[p * 64 + o] = tmin;
    }
    __syncthreads();

    // Phase OUT: 1280 float4s (64 o x 4 p x 5 q), 5 iters x 256 threads
    const float4* f4p = (const float4*)feats;
    float4* o4p = (float4*)out;
#pragma unroll
    for (int k = 0; k < 5; k++) {
        int i = t + k * 256;                // 0..1279
        int oi = i / 20, j = i - 20 * oi;   // oi 0..63
        int p = j / 5, q = j - 5 * p;
        float a = sA[oi], cc = sC[oi];
        // max_w relu(a*(u + t_w) + c) = relu(a*(u + (a>=0 ? max t : min t)) + c)
        float Ts = (a >= 0.0f) ? sTmax[p * 64 + oi] : sTmin[p * 64 + oi];
        float4 u4 = *(const float4*)&g_ut[((size_t)(pair0 + p) * 128 + oi) * 20 + 4 * q];
        size_t base4 = ((size_t)((b * 64 + oi) * 1024 + n0 + p)) * 5 + q;
        float4 f4 = f4p[base4];
        int vb = 4 * q;
        float4 r;
        r.x = f4.x + sm20[p * 20 + vb + 0] * fmaxf(fmaf(a, u4.x + Ts, cc), 0.0f);
        r.y = f4.y + sm20[p * 20 + vb + 1] * fmaxf(fmaf(a, u4.y + Ts, cc), 0.0f);
        r.z = f4.z + sm20[p * 20 + vb + 2] * fmaxf(fmaf(a, u4.z + Ts, cc), 0.0f);
        r.w = f4.w + sm20[p * 20 + vb + 3] * fmaxf(fmaf(a, u4.w + Ts, cc), 0.0f);
        o4p[base4] = r;
    }
}

extern "C" void kernel_launch(void* const* d_in, const int* in_sizes, int n_in,
                              void* d_out, int out_size) {
    const float* feats   = (const float*)d_in[0];  // (4,64,1024,20)
    const float* mask    = (const float*)d_in[1];  // (4,1024,20)
    const float* w_embed = (const float*)d_in[2];  // (32,64)
    const float* b_embed = (const float*)d_in[3];  // (32)
    const float* g_embed = (const float*)d_in[4];  // (32)
    const float* be_embed= (const float*)d_in[5];  // (32)
    const float* w_conv  = (const float*)d_in[6];  // (64,64)
    const float* g_conv  = (const float*)d_in[7];  // (64)
    const float* be_conv = (const float*)d_in[8];  // (64)
    float* out = (float*)d_out;

    k1_embed<<<1024, 320>>>(feats, mask, w_embed, b_embed);
    k3_conv<<<1024, 128>>>(mask, w_conv, g_embed, be_embed);
    k5_out<<<1024, 256>>>(feats, mask, g_conv, be_conv, out);
}

// round 17
// speedup vs baseline: 1.3385x; 1.0352x over previous
#include <cuda_runtime.h>
#include <math.h>

// Shapes (fixed by setup_inputs): B=4, C=64, C2=32, N=1024, V=20
#define NP 4096            // B*N pairs
#define CNT1 81920.0f      // B*N*V
#define CNT2 1638400.0f    // B*N*V*V

typedef unsigned long long ull;

// Scratch (allocation-free rule: __device__ globals; zero-initialized at load)
__device__ float g_xpre[NP * 32 * 20];        // masked pre-BN embed output, (pair, o, v)
__device__ float g_ut[(size_t)NP * 128 * 20]; // rows 0..63 = u, 64..127 = t, (pair, row, v)
__device__ float g_acc[384 * 256];            // stat counters, stride 256 floats (1024B -> distinct L2 slices)

// counter slots: [0,32)=sum1 [32,64)=sq1 [64,128)=SU [128,192)=SUQ [192,256)=ST [256,320)=STQ [320,384)=CROSS
// Replay protocol (graph-safe): K1-b0 zeroes [64,384); K5-b0 zeroes [0,64).
#define ACC(i) g_acc[(i) * 256]

// ---- packed fp32x2 helpers (proven in passing runs R4/R9/R11) ----
__device__ __forceinline__ void fma2(ull& d, ull a, ull b) {
    asm("fma.rn.f32x2 %0, %1, %2, %0;" : "+l"(d) : "l"(a), "l"(b));
}
__device__ __forceinline__ ull pack2(float x) {
    ull r; unsigned int u = __float_as_uint(x);
    asm("mov.b64 %0, {%1, %1};" : "=l"(r) : "r"(u));
    return r;
}
__device__ __forceinline__ float2 unpack2(ull v) {
    unsigned int lo, hi;
    asm("mov.b64 {%0, %1}, %2;" : "=r"(lo), "=r"(hi) : "l"(v));
    return make_float2(__uint_as_float(lo), __uint_as_float(hi));
}

// ---------------- K1: embed GEMM (f32x2) + mask + BN1 partial stats ----------------
// grid 1024, block 128 = 4 warps; warp w = pair blockIdx*4+w, lane = channel o.
// Each thread accumulates ALL 20 v (acc[10]) -> one weight LDS.64 serves 10 FFMA2:
// crossbar 7 cyc/(pair,c) vs 15 in the 97us baseline.
// R10/R14 bug was sf second dim 640; feats tile is 64 ch x 20 v = 1280 floats.
__global__ void __launch_bounds__(128, 4)
k1_embed(const float* __restrict__ feats, const float* __restrict__ mask,
         const float* __restrict__ w_embed, const float* __restrict__ b_embed) {
    __shared__ ull sW2[64 * 32];                     // packed (w,w), [c][o], 16KB
    __shared__ __align__(16) float sf[4][1280];      // feats tiles [p][c*20+v], 20KB  (1280 = 64*20!)
    __shared__ __align__(16) float smk[4][20];       // masks
    __shared__ float red_s[128], red_q[128];

    int t = threadIdx.x;
    int w = t >> 5, o = t & 31;
    int pair = blockIdx.x * 4 + w;

    if (blockIdx.x == 0) {                           // zero BN2 slots [64,384) for this replay
        ACC(64 + t) = 0.0f;                          // 64..191
        ACC(192 + t) = 0.0f;                         // 192..319
        if (t < 64) ACC(320 + t) = 0.0f;             // 320..383
    }

    for (int i = t; i < 2048; i += 128) {            // w_embed[o][c] -> sW2[c*32+o], packed
        int oo = i >> 6, c = i & 63;
        sW2[c * 32 + oo] = pack2(w_embed[i]);
    }
    if (t < 80) smk[t / 20][t % 20] = mask[blockIdx.x * 80 + t];
    for (int i = t; i < 1280; i += 128) {            // 4 pairs x 320 float4
        int p = i / 320;
        int r = i - p * 320;
        int c = r / 5, q = r - 5 * c;
        int pp = blockIdx.x * 4 + p;
        const float* fb = feats + (size_t)(pp >> 10) * 64 * 20480 + (pp & 1023) * 20;
        *(float4*)&sf[p][c * 20 + 4 * q] = *(const float4*)&fb[c * 20480 + 4 * q];
    }
    __syncthreads();

    ull acc[10];
    {
        ull b2 = pack2(b_embed[o]);
#pragma unroll
        for (int j = 0; j < 10; j++) acc[j] = b2;
    }
    const float* xb = sf[w];
#pragma unroll
    for (int c = 0; c < 64; c++) {
        ull w2 = sW2[c * 32 + o];                    // LDS.64, 32 consecutive -> conflict-free
#pragma unroll
        for (int q = 0; q < 5; q++) {
            ulonglong2 x = *(const ulonglong2*)&xb[c * 20 + 4 * q];  // warp broadcast
            fma2(acc[2 * q], x.x, w2);
            fma2(acc[2 * q + 1], x.y, w2);
        }
    }

    // epilogue: unpack, mask-multiply, float4 store, stats (proven K1 pattern)
    float ssum = 0.f, ssq = 0.f;
#pragma unroll
    for (int q = 0; q < 5; q++) {
        float2 f0 = unpack2(acc[2 * q]), f1 = unpack2(acc[2 * q + 1]);
        float4 m4 = *(const float4*)&smk[w][4 * q];
        float4 rr;
        rr.x = f0.x * m4.x; rr.y = f0.y * m4.y; rr.z = f1.x * m4.z; rr.w = f1.y * m4.w;
        *(float4*)&g_xpre[(size_t)pair * 640 + o * 20 + 4 * q] = rr;
        ssum += rr.x + rr.y + rr.z + rr.w;
        ssq += rr.x * rr.x + rr.y * rr.y + rr.z * rr.z + rr.w * rr.w;
    }
    red_s[t] = ssum; red_q[t] = ssq;
    __syncthreads();
    if (t < 32) {                                    // all 4 groups of 32 have o == t
        float s = 0.f, q = 0.f;
#pragma unroll
        for (int k = 0; k < 4; k++) { s += red_s[t + 32 * k]; q += red_q[t + 32 * k]; }
        atomicAdd(&ACC(t), s);
        atomicAdd(&ACC(32 + t), q);
    }
}

// ---------------- K3: BN1-finalize (per block) + [u;t] GEMM -> g_ut + BN2 partial stats ----------------
// grid 1024, block 128 (thread = output row: 0..63 -> u row, 64..127 -> t row), 4 pairs/block
// [R11-proven text verbatim]
__global__ void __launch_bounds__(128, 8)
k3_conv(const float* __restrict__ mask, const float* __restrict__ w_conv,
        const float* __restrict__ g_embed, const float* __restrict__ be_embed) {
    __shared__ __align__(16) float sx[640];  // activated x, [c][v]
    __shared__ __align__(16) float sm[20];
    __shared__ float sst[64];
    __shared__ float s_sc[32], s_sh[32];

    int t = threadIdx.x;
    if (t < 32) {                            // redundant per-block BN1 finalize (L2-cached counters)
        float inv = 1.0f / CNT1;
        float m = ACC(t) * inv;
        float var = ACC(32 + t) * inv - m * m;
        float sc = g_embed[t] * rsqrtf(var + 1e-5f);
        s_sc[t] = sc;
        s_sh[t] = be_embed[t] - m * sc;
    }

    float W[32];
    if (t < 64) {
#pragma unroll
        for (int c = 0; c < 32; c++) W[c] = w_conv[t * 64 + c] - w_conv[t * 64 + 32 + c];
    } else {
#pragma unroll
        for (int c = 0; c < 32; c++) W[c] = w_conv[(t - 64) * 64 + 32 + c];
    }

    float a_sum = 0.f, a_sq = 0.f, a_cr = 0.f;

    for (int p4 = 0; p4 < 4; p4++) {
        int pair = blockIdx.x * 4 + p4;
        __syncthreads();  // covers s_sc init (iter 0) and tile reuse
        if (t < 20) sm[t] = mask[pair * 20 + t];
        __syncthreads();
        // activate: 160 float4s, 128 threads
        for (int i = t; i < 160; i += 128) {
            int c = i / 5, q = i - 5 * c;
            float4 x = *(const float4*)&g_xpre[(size_t)pair * 640 + c * 20 + 4 * q];
            float sc = s_sc[c], sh = s_sh[c];
            int vb = 4 * q;
            float4 r;
            r.x = sm[vb + 0] * fmaxf(fmaf(x.x, sc, sh), 0.0f);
            r.y = sm[vb + 1] * fmaxf(fmaf(x.y, sc, sh), 0.0f);
            r.z = sm[vb + 2] * fmaxf(fmaf(x.z, sc, sh), 0.0f);
            r.w = sm[vb + 3] * fmaxf(fmaf(x.w, sc, sh), 0.0f);
            *(float4*)&sx[c * 20 + 4 * q] = r;
        }
        __syncthreads();

        ull acc[10];
#pragma unroll
        for (int j = 0; j < 10; j++) acc[j] = 0ull;
#pragma unroll
        for (int c = 0; c < 32; c++) {
            ull w2 = pack2(W[c]);
            const ulonglong2* row = (const ulonglong2*)&sx[c * 20];
#pragma unroll
            for (int q = 0; q < 5; q++) {
                ulonglong2 x = row[q];
                fma2(acc[2 * q], x.x, w2);
                fma2(acc[2 * q + 1], x.y, w2);
            }
        }
        // store row to g_ut (5 x STG.128)
        ulonglong2* gout = (ulonglong2*)&g_ut[((size_t)pair * 128 + t) * 20];
#pragma unroll
        for (int q = 0; q < 5; q++) {
            ulonglong2 s2; s2.x = acc[2 * q]; s2.y = acc[2 * q + 1];
            gout[q] = s2;
        }
        float psum = 0.f, psq = 0.f;
#pragma unroll
        for (int j = 0; j < 10; j++) {
            float2 f = unpack2(acc[j]);
            psum += f.x + f.y;
            psq += fmaf(f.x, f.x, f.y * f.y);
        }
        a_sum += psum; a_sq += psq;
        if (t >= 64) sst[t - 64] = psum;
        __syncthreads();
        if (t < 64) a_cr += psum * sst[t];  // per-pair (sum_v u[o])·(sum_v t[o]) cross term
    }

    if (t < 64) {
        atomicAdd(&ACC(64 + t), a_sum);
        atomicAdd(&ACC(128 + t), a_sq);
        atomicAdd(&ACC(320 + t), a_cr);
    } else {
        int o = t - 64;
        atomicAdd(&ACC(192 + o), a_sum);
        atomicAdd(&ACC(256 + o), a_sq);
    }
}

// ---------------- K5: BN2-finalize (per block) + streaming max-aggregate epilogue ----------------
// grid 1024, block 256; 4 pairs/block (same b per block).  [R11-proven text verbatim]
__global__ void __launch_bounds__(256, 6)
k5_out(const float* __restrict__ feats, const float* __restrict__ mask,
       const float* __restrict__ g_conv, const float* __restrict__ be_conv,
       float* __restrict__ out) {
    __shared__ float sTmax[4 * 64], sTmin[4 * 64];
    __shared__ float sm20[4 * 20];
    __shared__ float sA[64], sC[64];

    int t = threadIdx.x;
    int pair0 = blockIdx.x * 4;
    int b = pair0 >> 10, n0 = pair0 & 1023;

    if (t < 64) {                            // redundant per-block BN2 finalize
        float SU = ACC(64 + t), SUQ = ACC(128 + t);
        float ST = ACC(192 + t), STQ = ACC(256 + t);
        float CR = ACC(320 + t);
        float m = 20.0f * (SU + ST) / CNT2;
        float ey2 = (20.0f * (SUQ + STQ) + 2.0f * CR) / CNT2;
        float var = ey2 - m * m;
        float a = g_conv[t] * rsqrtf(var + 1e-5f);
        sA[t] = a;
        sC[t] = be_conv[t] - m * a;
    }
    if (blockIdx.x == 0 && t >= 192) ACC(t - 192) = 0.0f;   // zero BN1 slots [0,64) for next replay
    if (t >= 64 && t < 144) sm20[t - 64] = mask[pair0 * 20 + (t - 64)];

    // Phase T: thread = (p, o); reduce t-row over v
    {
        int p = t >> 6, o = t & 63;
        const float4* trow = (const float4*)&g_ut[((size_t)(pair0 + p) * 128 + 64 + o) * 20];
        float tmax = -3.4e38f, tmin = 3.4e38f;
#pragma unroll
        for (int q = 0; q < 5; q++) {
            float4 x = trow[q];
            tmax = fmaxf(tmax, fmaxf(fmaxf(x.x, x.y), fmaxf(x.z, x.w)));
            tmin = fminf(tmin, fminf(fminf(x.x, x.y), fminf(x.z, x.w)));
        }
        sTmax[p * 64 + o] = tmax;
        sTmin[p * 64 + o] = tmin;
    }
    __syncthreads();

    // Phase OUT: 1280 float4s (64 o x 4 p x 5 q), 5 iters x 256 threads
    const float4* f4p = (const float4*)feats;
    float4* o4p = (float4*)out;
#pragma unroll
    for (int k = 0; k < 5; k++) {
        int i = t + k * 256;                // 0..1279
        int oi = i / 20, j = i - 20 * oi;   // oi 0..63
        int p = j / 5, q = j - 5 * p;
        float a = sA[oi], cc = sC[oi];
        // max_w relu(a*(u + t_w) + c) = relu(a*(u + (a>=0 ? max t : min t)) + c)
        float Ts = (a >= 0.0f) ? sTmax[p * 64 + oi] : sTmin[p * 64 + oi];
        float4 u4 = *(const float4*)&g_ut[((size_t)(pair0 + p) * 128 + oi) * 20 + 4 * q];
        size_t base4 = ((size_t)((b * 64 + oi) * 1024 + n0 + p)) * 5 + q;
        float4 f4 = f4p[base4];
        int vb = 4 * q;
        float4 r;
        r.x = f4.x + sm20[p * 20 + vb + 0] * fmaxf(fmaf(a, u4.x + Ts, cc), 0.0f);
        r.y = f4.y + sm20[p * 20 + vb + 1] * fmaxf(fmaf(a, u4.y + Ts, cc), 0.0f);
        r.z = f4.z + sm20[p * 20 + vb + 2] * fmaxf(fmaf(a, u4.z + Ts, cc), 0.0f);
        r.w = f4.w + sm20[p * 20 + vb + 3] * fmaxf(fmaf(a, u4.w + Ts, cc), 0.0f);
        o4p[base4] = r;
    }
}

extern "C" void kernel_launch(void* const* d_in, const int* in_sizes, int n_in,
                              void* d_out, int out_size) {
    const float* feats   = (const float*)d_in[0];  // (4,64,1024,20)
    const float* mask    = (const float*)d_in[1];  // (4,1024,20)
    const float* w_embed = (const float*)d_in[2];  // (32,64)
    const float* b_embed = (const float*)d_in[3];  // (32)
    const float* g_embed = (const float*)d_in[4];  // (32)
    const float* be_embed= (const float*)d_in[5];  // (32)
    const float* w_conv  = (const float*)d_in[6];  // (64,64)
    const float* g_conv  = (const float*)d_in[7];  // (64)
    const float* be_conv = (const float*)d_in[8];  // (64)
    float* out = (float*)d_out;

    k1_embed<<<1024, 128>>>(feats, mask, w_embed, b_embed);
    k3_conv<<<1024, 128>>>(mask, w_conv, g_embed, be_embed);
    k5_out<<<1024, 256>>>(feats, mask, g_conv, be_conv, out);
}